// round 1
// baseline (speedup 1.0000x reference)
#include <cuda_runtime.h>
#include <math.h>

// Problem constants
#define BB   2
#define NN   2048
#define DIMM 1024
#define HH   16
#define DHH  64
#define MM   (BB*NN)          // 4096 tokens

// Scratch (allocation-free rule: __device__ globals)
__device__ float g_y  [MM * DIMM];        // LN output            16 MB
__device__ float g_qkv[MM * 3 * DIMM];    // qkv (normed q/k)     48 MB
__device__ float g_o  [MM * DIMM];        // attention out        16 MB
__device__ float g_p  [MM * DIMM];        // c_proj out           16 MB

__device__ __forceinline__ float warp_sum(float v) {
#pragma unroll
    for (int o = 16; o; o >>= 1) v += __shfl_xor_sync(0xffffffffu, v, o);
    return v;
}

// ---------------------------------------------------------------------------
// LayerNorm: one block per token row (1024 elems), 256 threads * float4
// ---------------------------------------------------------------------------
__global__ void __launch_bounds__(256) ln_kernel(const float* __restrict__ x,
                                                 const float* __restrict__ g,
                                                 const float* __restrict__ b,
                                                 float* __restrict__ y) {
    int row = blockIdx.x;
    int t = threadIdx.x;
    const float* xr = x + (size_t)row * DIMM;
    float4 v = *(const float4*)(xr + t * 4);
    float s  = v.x + v.y + v.z + v.w;
    float ss = v.x*v.x + v.y*v.y + v.z*v.z + v.w*v.w;
    __shared__ float red[16];
    float s1 = warp_sum(s), s2 = warp_sum(ss);
    int w = t >> 5, lane = t & 31;
    if (lane == 0) { red[w] = s1; red[8 + w] = s2; }
    __syncthreads();
    float tot = 0.f, tot2 = 0.f;
#pragma unroll
    for (int i = 0; i < 8; i++) { tot += red[i]; tot2 += red[8 + i]; }
    float mu  = tot  * (1.f / DIMM);
    float var = tot2 * (1.f / DIMM) - mu * mu;
    float inv = rsqrtf(var + 1e-5f);
    float4 gv = *(const float4*)(g + t * 4);
    float4 bv = *(const float4*)(b + t * 4);
    float4 o;
    o.x = (v.x - mu) * inv * gv.x + bv.x;
    o.y = (v.y - mu) * inv * gv.y + bv.y;
    o.z = (v.z - mu) * inv * gv.z + bv.z;
    o.w = (v.w - mu) * inv * gv.w + bv.w;
    *(float4*)(y + (size_t)row * DIMM + t * 4) = o;
}

// ---------------------------------------------------------------------------
// L2-normalize q and k head rows in-place in qkv. One warp per 64-elem row.
// rows = 4096 tokens * 16 heads * 2 (q,k) = 131072
// ---------------------------------------------------------------------------
__global__ void __launch_bounds__(256) l2n_kernel(float* __restrict__ qkv) {
    int gw   = (blockIdx.x * 256 + threadIdx.x) >> 5;
    int lane = threadIdx.x & 31;
    int token = gw >> 5;
    int rem   = gw & 31;
    int h = rem >> 1, isk = rem & 1;
    float* p = qkv + (size_t)token * (3 * DIMM) + isk * DIMM + h * DHH;
    float a = p[lane], c = p[lane + 32];
    float ss = warp_sum(a * a + c * c);
    float n = sqrtf(ss);
    float inv = 1.f / fmaxf(n, 1e-12f);
    p[lane]      = a * inv;
    p[lane + 32] = c * inv;
}

// ---------------------------------------------------------------------------
// SGEMM: C[M,N] = A[M,K] @ B (+bias). TRANSB=1 means B is [N,K] (C = A @ B^T).
// 128x128 block tile, K-step 8, 256 threads, 8x8 per thread.
// ---------------------------------------------------------------------------
template <bool TRANSB>
__global__ void __launch_bounds__(256) sgemm_kernel(const float* __restrict__ A,
                                                    const float* __restrict__ Bm,
                                                    const float* __restrict__ bias,
                                                    float* __restrict__ C,
                                                    int M, int N, int K) {
    __shared__ float As[8][128];
    __shared__ float Bs[8][128];
    int tid = threadIdx.x;
    int bm = blockIdx.y * 128, bn = blockIdx.x * 128;
    int lrow = tid >> 1;            // 0..127
    int lcol = (tid & 1) * 4;       // 0 or 4
    int br = tid >> 5, bc = (tid & 31) * 4;
    int trow = (tid >> 4) << 3, tcol = (tid & 15) << 3;

    float acc[8][8];
#pragma unroll
    for (int i = 0; i < 8; i++)
#pragma unroll
        for (int j = 0; j < 8; j++) acc[i][j] = 0.f;

    for (int k0 = 0; k0 < K; k0 += 8) {
        float4 a4 = *(const float4*)(A + (size_t)(bm + lrow) * K + k0 + lcol);
        As[lcol + 0][lrow] = a4.x;
        As[lcol + 1][lrow] = a4.y;
        As[lcol + 2][lrow] = a4.z;
        As[lcol + 3][lrow] = a4.w;
        if (!TRANSB) {
            *(float4*)&Bs[br][bc] =
                *(const float4*)(Bm + (size_t)(k0 + br) * N + bn + bc);
        } else {
            float4 b4 = *(const float4*)(Bm + (size_t)(bn + lrow) * K + k0 + lcol);
            Bs[lcol + 0][lrow] = b4.x;
            Bs[lcol + 1][lrow] = b4.y;
            Bs[lcol + 2][lrow] = b4.z;
            Bs[lcol + 3][lrow] = b4.w;
        }
        __syncthreads();
#pragma unroll
        for (int kk = 0; kk < 8; kk++) {
            float ra[8], rb[8];
            *(float4*)(ra)     = *(const float4*)&As[kk][trow];
            *(float4*)(ra + 4) = *(const float4*)&As[kk][trow + 4];
            *(float4*)(rb)     = *(const float4*)&Bs[kk][tcol];
            *(float4*)(rb + 4) = *(const float4*)&Bs[kk][tcol + 4];
#pragma unroll
            for (int i = 0; i < 8; i++)
#pragma unroll
                for (int j = 0; j < 8; j++) acc[i][j] += ra[i] * rb[j];
        }
        __syncthreads();
    }

    float bb[8];
#pragma unroll
    for (int j = 0; j < 8; j++) bb[j] = bias ? bias[bn + tcol + j] : 0.f;
#pragma unroll
    for (int i = 0; i < 8; i++) {
        size_t off = (size_t)(bm + trow + i) * N + bn + tcol;
        float4 r0, r1;
        r0.x = acc[i][0] + bb[0]; r0.y = acc[i][1] + bb[1];
        r0.z = acc[i][2] + bb[2]; r0.w = acc[i][3] + bb[3];
        r1.x = acc[i][4] + bb[4]; r1.y = acc[i][5] + bb[5];
        r1.z = acc[i][6] + bb[6]; r1.w = acc[i][7] + bb[7];
        *(float4*)(C + off)     = r0;
        *(float4*)(C + off + 4) = r1;
    }
}

// ---------------------------------------------------------------------------
// Causal flash-attention (fp32). One block = one (b, h, 64-query tile).
// 256 threads = 64 rows x 4 col-groups. Online softmax, P staged in smem.
// smem strides: q/k/v padded to 68 floats (conflict-free k reads with
// interleaved j = 4*jj+cq), P stored [j][row] with stride 65.
// ---------------------------------------------------------------------------
#define ATT_SMEM ((3 * 64 * 68 + 64 * 65) * 4)

__global__ void __launch_bounds__(256) attn_kernel(const float* __restrict__ qkv,
                                                   float* __restrict__ o) {
    extern __shared__ float sm[];
    float* sq = sm;
    float* sk = sm + 64 * 68;
    float* sv = sm + 2 * 64 * 68;
    float* sp = sm + 3 * 64 * 68;

    int bh = blockIdx.y;
    int b = bh >> 4, h = bh & 15;
    int q0 = blockIdx.x * 64;
    const float* base = qkv + (size_t)b * NN * (3 * DIMM);
    int tid = threadIdx.x;

    // load q tile [64 x 64]
    for (int i = tid; i < 64 * 16; i += 256) {
        int r = i >> 4, c = (i & 15) << 2;
        *(float4*)&sq[r * 68 + c] =
            *(const float4*)(base + (size_t)(q0 + r) * (3 * DIMM) + h * DHH + c);
    }

    int row = tid >> 2, cq = tid & 3;
    float m = -1e30f, l = 0.f;
    float acc[16];
#pragma unroll
    for (int i = 0; i < 16; i++) acc[i] = 0.f;

    for (int j0 = 0; j0 <= q0; j0 += 64) {
        __syncthreads();  // prev PV done with sk/sv & sp; q loaded (first iter)
        for (int i = tid; i < 64 * 16; i += 256) {
            int r = i >> 4, c = (i & 15) << 2;
            const float* src = base + (size_t)(j0 + r) * (3 * DIMM) + h * DHH + c;
            *(float4*)&sk[r * 68 + c] = *(const float4*)(src + DIMM);
            *(float4*)&sv[r * 68 + c] = *(const float4*)(src + 2 * DIMM);
        }
        __syncthreads();

        // S = q . k^T   (thread owns row, keys j = 4*jj + cq)
        float s[16];
#pragma unroll
        for (int jj = 0; jj < 16; jj++) s[jj] = 0.f;
#pragma unroll
        for (int d = 0; d < 64; d += 4) {
            float4 q4 = *(const float4*)&sq[row * 68 + d];
#pragma unroll
            for (int jj = 0; jj < 16; jj++) {
                float4 k4 = *(const float4*)&sk[(jj * 4 + cq) * 68 + d];
                s[jj] += q4.x * k4.x + q4.y * k4.y + q4.z * k4.z + q4.w * k4.w;
            }
        }

        // scale + causal mask + row max
        float mx = -1e30f;
#pragma unroll
        for (int jj = 0; jj < 16; jj++) {
            int key = j0 + jj * 4 + cq;
            float sv_ = s[jj] * 8.0f;
            sv_ = (key > q0 + row) ? -1e30f : sv_;
            s[jj] = sv_;
            mx = fmaxf(mx, sv_);
        }
        mx = fmaxf(mx, __shfl_xor_sync(0xffffffffu, mx, 1));
        mx = fmaxf(mx, __shfl_xor_sync(0xffffffffu, mx, 2));
        float newm = fmaxf(m, mx);
        float alpha = __expf(m - newm);

        float lsum = 0.f;
#pragma unroll
        for (int jj = 0; jj < 16; jj++) {
            float p = __expf(s[jj] - newm);
            sp[(jj * 4 + cq) * 65 + row] = p;
            lsum += p;
        }
        lsum += __shfl_xor_sync(0xffffffffu, lsum, 1);
        lsum += __shfl_xor_sync(0xffffffffu, lsum, 2);
        l = l * alpha + lsum;
        m = newm;
#pragma unroll
        for (int i = 0; i < 16; i++) acc[i] *= alpha;
        __syncwarp();

        // O += P @ V  (thread owns dims d = cq*4 + 16*ii + 0..3)
#pragma unroll 4
        for (int j = 0; j < 64; j++) {
            float p = sp[j * 65 + row];
#pragma unroll
            for (int ii = 0; ii < 4; ii++) {
                float4 v4 = *(const float4*)&sv[j * 68 + cq * 4 + ii * 16];
                acc[ii * 4 + 0] += p * v4.x;
                acc[ii * 4 + 1] += p * v4.y;
                acc[ii * 4 + 2] += p * v4.z;
                acc[ii * 4 + 3] += p * v4.w;
            }
        }
    }

    float invl = 1.f / l;
    float* op = o + ((size_t)(b * NN + q0 + row)) * DIMM + h * DHH;
#pragma unroll
    for (int ii = 0; ii < 4; ii++) {
        float4 r;
        r.x = acc[ii * 4 + 0] * invl;
        r.y = acc[ii * 4 + 1] * invl;
        r.z = acc[ii * 4 + 2] * invl;
        r.w = acc[ii * 4 + 3] * invl;
        *(float4*)(op + cq * 4 + ii * 16) = r;
    }
}

// ---------------------------------------------------------------------------
extern "C" void kernel_launch(void* const* d_in, const int* in_sizes, int n_in,
                              void* d_out, int out_size) {
    const float* x   = (const float*)d_in[0];
    const float* g   = (const float*)d_in[1];
    const float* b   = (const float*)d_in[2];
    const float* caw = (const float*)d_in[3];
    const float* cab = (const float*)d_in[4];
    const float* cpw = (const float*)d_in[5];
    const float* cpb = (const float*)d_in[6];
    const float* tow = (const float*)d_in[7];
    float* out = (float*)d_out;

    float *y, *qkv, *ob, *pb;
    cudaGetSymbolAddress((void**)&y,   g_y);
    cudaGetSymbolAddress((void**)&qkv, g_qkv);
    cudaGetSymbolAddress((void**)&ob,  g_o);
    cudaGetSymbolAddress((void**)&pb,  g_p);

    cudaFuncSetAttribute(attn_kernel,
                         cudaFuncAttributeMaxDynamicSharedMemorySize, ATT_SMEM);

    // 1. LayerNorm
    ln_kernel<<<MM, 256>>>(x, g, b, y);

    // 2. qkv = y @ c_attn_w + c_attn_b   [4096 x 3072]
    sgemm_kernel<false><<<dim3(3 * DIMM / 128, MM / 128), 256>>>(
        y, caw, cab, qkv, MM, 3 * DIMM, DIMM);

    // 3. L2-normalize q, k head rows in place
    l2n_kernel<<<(MM * HH * 2 * 32) / 256, 256>>>(qkv);

    // 4. causal cosine-sim attention -> merged heads in g_o
    attn_kernel<<<dim3(NN / 64, BB * HH), 256, ATT_SMEM>>>(qkv, ob);

    // 5. p = o @ c_proj_w + c_proj_b
    sgemm_kernel<false><<<dim3(DIMM / 128, MM / 128), 256>>>(
        ob, cpw, cpb, pb, MM, DIMM, DIMM);

    // 6. out = p @ to_out_w^T
    sgemm_kernel<true><<<dim3(DIMM / 128, MM / 128), 256>>>(
        pb, tow, (const float*)nullptr, out, MM, DIMM, DIMM);
}

// round 3
// speedup vs baseline: 1.2860x; 1.2860x over previous
#include <cuda_runtime.h>
#include <cuda_bf16.h>
#include <cstdint>
#include <math.h>

typedef unsigned int u32;

// Problem constants
#define BB   2
#define NN   2048
#define DIMM 1024
#define HH   16
#define DHH  64
#define MM   (BB*NN)          // 4096 tokens

// Scratch (allocation-free rule: __device__ globals)
__device__ float g_y  [MM * DIMM];        // LN output
__device__ float g_qkv[MM * 3 * DIMM];    // qkv (normed q/k)
__device__ float g_o  [MM * DIMM];        // attention out
__device__ float g_p  [MM * DIMM];        // c_proj out

__device__ __forceinline__ float warp_sum(float v) {
#pragma unroll
    for (int o = 16; o; o >>= 1) v += __shfl_xor_sync(0xffffffffu, v, o);
    return v;
}

// ---------------------------------------------------------------------------
// LayerNorm
// ---------------------------------------------------------------------------
__global__ void __launch_bounds__(256) ln_kernel(const float* __restrict__ x,
                                                 const float* __restrict__ g,
                                                 const float* __restrict__ b,
                                                 float* __restrict__ y) {
    int row = blockIdx.x;
    int t = threadIdx.x;
    const float* xr = x + (size_t)row * DIMM;
    float4 v = *(const float4*)(xr + t * 4);
    float s  = v.x + v.y + v.z + v.w;
    float ss = v.x*v.x + v.y*v.y + v.z*v.z + v.w*v.w;
    __shared__ float red[16];
    float s1 = warp_sum(s), s2 = warp_sum(ss);
    int w = t >> 5, lane = t & 31;
    if (lane == 0) { red[w] = s1; red[8 + w] = s2; }
    __syncthreads();
    float tot = 0.f, tot2 = 0.f;
#pragma unroll
    for (int i = 0; i < 8; i++) { tot += red[i]; tot2 += red[8 + i]; }
    float mu  = tot  * (1.f / DIMM);
    float var = tot2 * (1.f / DIMM) - mu * mu;
    float inv = rsqrtf(var + 1e-5f);
    float4 gv = *(const float4*)(g + t * 4);
    float4 bv = *(const float4*)(b + t * 4);
    float4 o;
    o.x = (v.x - mu) * inv * gv.x + bv.x;
    o.y = (v.y - mu) * inv * gv.y + bv.y;
    o.z = (v.z - mu) * inv * gv.z + bv.z;
    o.w = (v.w - mu) * inv * gv.w + bv.w;
    *(float4*)(y + (size_t)row * DIMM + t * 4) = o;
}

// ---------------------------------------------------------------------------
// L2-normalize q and k head rows in-place in qkv. One warp per 64-elem row.
// ---------------------------------------------------------------------------
__global__ void __launch_bounds__(256) l2n_kernel(float* __restrict__ qkv) {
    int gw   = (blockIdx.x * 256 + threadIdx.x) >> 5;
    int lane = threadIdx.x & 31;
    int token = gw >> 5;
    int rem   = gw & 31;
    int h = rem >> 1, isk = rem & 1;
    float* p = qkv + (size_t)token * (3 * DIMM) + isk * DIMM + h * DHH;
    float a = p[lane], c = p[lane + 32];
    float ss = warp_sum(a * a + c * c);
    float n = sqrtf(ss);
    float inv = 1.f / fmaxf(n, 1e-12f);
    p[lane]      = a * inv;
    p[lane + 32] = c * inv;
}

// ---------------------------------------------------------------------------
// bf16x3 tensor-core GEMM: C[M,N] = A[M,K] @ B (+bias), fp32 in/out.
// x = x_hi + x_lo (bf16 each); C = Ah*Bh + Ah*Bl + Al*Bh (fp32 accum).
// Block 128x128, BK=16, 256 threads = 8 warps (4m x 2n), warp tile 32x64.
// TRANSB=1: B is [N,K], C = A @ B^T.
// ---------------------------------------------------------------------------
#define SAK 24     // As row stride (bf16 elems), conflict-free ldmatrix
#define SBN 136    // Bs [k][n] row stride (non-trans path)
#define SBT 24     // Bs [n][k] row stride (TRANSB path)

__device__ __forceinline__ void ldm4(u32* r, const __nv_bfloat16* p) {
    u32 a = (u32)__cvta_generic_to_shared(p);
    asm volatile("ldmatrix.sync.aligned.m8n8.x4.shared.b16 {%0,%1,%2,%3}, [%4];"
        : "=r"(r[0]), "=r"(r[1]), "=r"(r[2]), "=r"(r[3]) : "r"(a));
}
__device__ __forceinline__ void ldm4t(u32* r, const __nv_bfloat16* p) {
    u32 a = (u32)__cvta_generic_to_shared(p);
    asm volatile("ldmatrix.sync.aligned.m8n8.x4.trans.shared.b16 {%0,%1,%2,%3}, [%4];"
        : "=r"(r[0]), "=r"(r[1]), "=r"(r[2]), "=r"(r[3]) : "r"(a));
}
__device__ __forceinline__ void mma16816(float* c, const u32* a, const u32* b) {
    asm volatile("mma.sync.aligned.m16n8k16.row.col.f32.bf16.bf16.f32 "
        "{%0,%1,%2,%3}, {%4,%5,%6,%7}, {%8,%9}, {%0,%1,%2,%3};"
        : "+f"(c[0]), "+f"(c[1]), "+f"(c[2]), "+f"(c[3])
        : "r"(a[0]), "r"(a[1]), "r"(a[2]), "r"(a[3]), "r"(b[0]), "r"(b[1]));
}

__device__ __forceinline__ u32 p2(float a, float b) {
    __nv_bfloat162 t = __floats2bfloat162_rn(a, b);
    return *reinterpret_cast<u32*>(&t);
}
__device__ __forceinline__ void split_store4(float4 v, __nv_bfloat16* ph,
                                             __nv_bfloat16* pl) {
    float hx = __bfloat162float(__float2bfloat16_rn(v.x));
    float hy = __bfloat162float(__float2bfloat16_rn(v.y));
    float hz = __bfloat162float(__float2bfloat16_rn(v.z));
    float hw = __bfloat162float(__float2bfloat16_rn(v.w));
    *reinterpret_cast<uint2*>(ph) = make_uint2(p2(hx, hy), p2(hz, hw));
    *reinterpret_cast<uint2*>(pl) =
        make_uint2(p2(v.x - hx, v.y - hy), p2(v.z - hz, v.w - hw));
}

template <bool TRANSB, bool HASBIAS>
__global__ void __launch_bounds__(256) hgemm_kernel(const float* __restrict__ A,
                                                    const float* __restrict__ Bm,
                                                    const float* __restrict__ bias,
                                                    float* __restrict__ C,
                                                    int M, int N, int K) {
    __shared__ __align__(16) __nv_bfloat16 As_h[128 * SAK];
    __shared__ __align__(16) __nv_bfloat16 As_l[128 * SAK];
    __shared__ __align__(16) __nv_bfloat16 Bs_h[3072];   // max(16*136, 128*24)
    __shared__ __align__(16) __nv_bfloat16 Bs_l[3072];

    int tid = threadIdx.x;
    int bm = blockIdx.y * 128, bn = blockIdx.x * 128;

    // A loader: rows tid>>2 and +64, cols (tid&3)*4
    int ar = tid >> 2, ac = (tid & 3) * 4;
    const float* Ap0 = A + (size_t)(bm + ar) * K + ac;
    const float* Ap1 = Ap0 + (size_t)64 * K;

    // B loader
    const float* Bp0;
    const float* Bp1;
    int bkr = 0, bnc = 0, tnr = 0, tkc = 0;
    if (!TRANSB) {
        bkr = tid >> 4;            // k row 0..15
        bnc = (tid & 15) * 8;      // n offset
        Bp0 = Bm + (size_t)bkr * N + bn + bnc;
        Bp1 = Bp0 + 4;
    } else {
        tnr = tid >> 1;            // n row 0..127
        tkc = (tid & 1) * 8;       // k offset
        Bp0 = Bm + (size_t)(bn + tnr) * K + tkc;
        Bp1 = Bp0 + 4;
    }

    float4 ra0 = *(const float4*)Ap0;
    float4 ra1 = *(const float4*)Ap1;
    float4 rb0 = *(const float4*)Bp0;
    float4 rb1 = *(const float4*)Bp1;

    int wid = tid >> 5, lane = tid & 31;
    int wm = (wid & 3) * 32, wn = (wid >> 2) * 64;
    int grp = lane >> 3, lr = lane & 7;

    // ldmatrix source indices (element offsets, hi/lo share them)
    int aidx[2];
    {
        int arow = wm + ((grp & 1) << 3) + lr;
        int acol = (grp & 2) ? 8 : 0;
        aidx[0] = arow * SAK + acol;
        aidx[1] = (arow + 16) * SAK + acol;
    }
    int bidx[4];
#pragma unroll
    for (int nb = 0; nb < 4; nb++) {
        if (!TRANSB) {
            int krow = ((grp & 1) << 3) + lr;
            int ncol = wn + nb * 16 + ((grp & 2) ? 8 : 0);
            bidx[nb] = krow * SBN + ncol;
        } else {
            int nrow = wn + nb * 16 + ((grp & 2) ? 8 : 0) + lr;
            int kcol = (grp & 1) ? 8 : 0;
            bidx[nb] = nrow * SBT + kcol;
        }
    }

    float acc[2][8][4];
#pragma unroll
    for (int i = 0; i < 2; i++)
#pragma unroll
        for (int j = 0; j < 8; j++)
#pragma unroll
            for (int q = 0; q < 4; q++) acc[i][j][q] = 0.f;

    for (int k0 = 0; k0 < K; k0 += 16) {
        // stage current tile to smem (bf16 hi/lo split)
        split_store4(ra0, &As_h[ar * SAK + ac], &As_l[ar * SAK + ac]);
        split_store4(ra1, &As_h[(ar + 64) * SAK + ac], &As_l[(ar + 64) * SAK + ac]);
        if (!TRANSB) {
            split_store4(rb0, &Bs_h[bkr * SBN + bnc], &Bs_l[bkr * SBN + bnc]);
            split_store4(rb1, &Bs_h[bkr * SBN + bnc + 4], &Bs_l[bkr * SBN + bnc + 4]);
        } else {
            split_store4(rb0, &Bs_h[tnr * SBT + tkc], &Bs_l[tnr * SBT + tkc]);
            split_store4(rb1, &Bs_h[tnr * SBT + tkc + 4], &Bs_l[tnr * SBT + tkc + 4]);
        }
        __syncthreads();

        // prefetch next tile into registers
        if (k0 + 16 < K) {
            Ap0 += 16; Ap1 += 16;
            ra0 = *(const float4*)Ap0;
            ra1 = *(const float4*)Ap1;
            if (!TRANSB) { Bp0 += (size_t)16 * N; Bp1 += (size_t)16 * N; }
            else         { Bp0 += 16;             Bp1 += 16; }
            rb0 = *(const float4*)Bp0;
            rb1 = *(const float4*)Bp1;
        }

        // fragments
        u32 ah[2][4], al[2][4];
        ldm4(ah[0], &As_h[aidx[0]]);
        ldm4(ah[1], &As_h[aidx[1]]);
        ldm4(al[0], &As_l[aidx[0]]);
        ldm4(al[1], &As_l[aidx[1]]);

        u32 bh[8][2], bl[8][2];
#pragma unroll
        for (int nb = 0; nb < 4; nb++) {
            u32 r[4];
            if (!TRANSB) ldm4t(r, &Bs_h[bidx[nb]]);
            else         ldm4 (r, &Bs_h[bidx[nb]]);
            bh[2 * nb][0] = r[0]; bh[2 * nb][1] = r[1];
            bh[2 * nb + 1][0] = r[2]; bh[2 * nb + 1][1] = r[3];
            if (!TRANSB) ldm4t(r, &Bs_l[bidx[nb]]);
            else         ldm4 (r, &Bs_l[bidx[nb]]);
            bl[2 * nb][0] = r[0]; bl[2 * nb][1] = r[1];
            bl[2 * nb + 1][0] = r[2]; bl[2 * nb + 1][1] = r[3];
        }

#pragma unroll
        for (int mi = 0; mi < 2; mi++)
#pragma unroll
            for (int nf = 0; nf < 8; nf++) {
                mma16816(acc[mi][nf], ah[mi], bh[nf]);
                mma16816(acc[mi][nf], ah[mi], bl[nf]);
                mma16816(acc[mi][nf], al[mi], bh[nf]);
            }
        __syncthreads();
    }

    // epilogue
    int r = lane >> 2, c2 = (lane & 3) * 2;
#pragma unroll
    for (int nf = 0; nf < 8; nf++) {
        int col = bn + wn + nf * 8 + c2;
        float b0v = 0.f, b1v = 0.f;
        if (HASBIAS) { b0v = bias[col]; b1v = bias[col + 1]; }
#pragma unroll
        for (int mi = 0; mi < 2; mi++) {
            int row0 = bm + wm + mi * 16 + r;
            float2 v0 = make_float2(acc[mi][nf][0] + b0v, acc[mi][nf][1] + b1v);
            float2 v1 = make_float2(acc[mi][nf][2] + b0v, acc[mi][nf][3] + b1v);
            *(float2*)(C + (size_t)row0 * N + col) = v0;
            *(float2*)(C + (size_t)(row0 + 8) * N + col) = v1;
        }
    }
}

// ---------------------------------------------------------------------------
// Causal flash-attention (fp32), unchanged from R1.
// ---------------------------------------------------------------------------
#define ATT_SMEM ((3 * 64 * 68 + 64 * 65) * 4)

__global__ void __launch_bounds__(256) attn_kernel(const float* __restrict__ qkv,
                                                   float* __restrict__ o) {
    extern __shared__ float sm[];
    float* sq = sm;
    float* sk = sm + 64 * 68;
    float* sv = sm + 2 * 64 * 68;
    float* sp = sm + 3 * 64 * 68;

    int bh = blockIdx.y;
    int b = bh >> 4, h = bh & 15;
    int q0 = blockIdx.x * 64;
    const float* base = qkv + (size_t)b * NN * (3 * DIMM);
    int tid = threadIdx.x;

    for (int i = tid; i < 64 * 16; i += 256) {
        int r = i >> 4, c = (i & 15) << 2;
        *(float4*)&sq[r * 68 + c] =
            *(const float4*)(base + (size_t)(q0 + r) * (3 * DIMM) + h * DHH + c);
    }

    int row = tid >> 2, cq = tid & 3;
    float m = -1e30f, l = 0.f;
    float acc[16];
#pragma unroll
    for (int i = 0; i < 16; i++) acc[i] = 0.f;

    for (int j0 = 0; j0 <= q0; j0 += 64) {
        __syncthreads();
        for (int i = tid; i < 64 * 16; i += 256) {
            int r = i >> 4, c = (i & 15) << 2;
            const float* src = base + (size_t)(j0 + r) * (3 * DIMM) + h * DHH + c;
            *(float4*)&sk[r * 68 + c] = *(const float4*)(src + DIMM);
            *(float4*)&sv[r * 68 + c] = *(const float4*)(src + 2 * DIMM);
        }
        __syncthreads();

        float s[16];
#pragma unroll
        for (int jj = 0; jj < 16; jj++) s[jj] = 0.f;
#pragma unroll
        for (int d = 0; d < 64; d += 4) {
            float4 q4 = *(const float4*)&sq[row * 68 + d];
#pragma unroll
            for (int jj = 0; jj < 16; jj++) {
                float4 k4 = *(const float4*)&sk[(jj * 4 + cq) * 68 + d];
                s[jj] += q4.x * k4.x + q4.y * k4.y + q4.z * k4.z + q4.w * k4.w;
            }
        }

        float mx = -1e30f;
#pragma unroll
        for (int jj = 0; jj < 16; jj++) {
            int key = j0 + jj * 4 + cq;
            float sv_ = s[jj] * 8.0f;
            sv_ = (key > q0 + row) ? -1e30f : sv_;
            s[jj] = sv_;
            mx = fmaxf(mx, sv_);
        }
        mx = fmaxf(mx, __shfl_xor_sync(0xffffffffu, mx, 1));
        mx = fmaxf(mx, __shfl_xor_sync(0xffffffffu, mx, 2));
        float newm = fmaxf(m, mx);
        float alpha = __expf(m - newm);

        float lsum = 0.f;
#pragma unroll
        for (int jj = 0; jj < 16; jj++) {
            float p = __expf(s[jj] - newm);
            sp[(jj * 4 + cq) * 65 + row] = p;
            lsum += p;
        }
        lsum += __shfl_xor_sync(0xffffffffu, lsum, 1);
        lsum += __shfl_xor_sync(0xffffffffu, lsum, 2);
        l = l * alpha + lsum;
        m = newm;
#pragma unroll
        for (int i = 0; i < 16; i++) acc[i] *= alpha;
        __syncwarp();

#pragma unroll 4
        for (int j = 0; j < 64; j++) {
            float p = sp[j * 65 + row];
#pragma unroll
            for (int ii = 0; ii < 4; ii++) {
                float4 v4 = *(const float4*)&sv[j * 68 + cq * 4 + ii * 16];
                acc[ii * 4 + 0] += p * v4.x;
                acc[ii * 4 + 1] += p * v4.y;
                acc[ii * 4 + 2] += p * v4.z;
                acc[ii * 4 + 3] += p * v4.w;
            }
        }
    }

    float invl = 1.f / l;
    float* op = o + ((size_t)(b * NN + q0 + row)) * DIMM + h * DHH;
#pragma unroll
    for (int ii = 0; ii < 4; ii++) {
        float4 r;
        r.x = acc[ii * 4 + 0] * invl;
        r.y = acc[ii * 4 + 1] * invl;
        r.z = acc[ii * 4 + 2] * invl;
        r.w = acc[ii * 4 + 3] * invl;
        *(float4*)(op + cq * 4 + ii * 16) = r;
    }
}

// ---------------------------------------------------------------------------
extern "C" void kernel_launch(void* const* d_in, const int* in_sizes, int n_in,
                              void* d_out, int out_size) {
    const float* x   = (const float*)d_in[0];
    const float* g   = (const float*)d_in[1];
    const float* b   = (const float*)d_in[2];
    const float* caw = (const float*)d_in[3];
    const float* cab = (const float*)d_in[4];
    const float* cpw = (const float*)d_in[5];
    const float* cpb = (const float*)d_in[6];
    const float* tow = (const float*)d_in[7];
    float* out = (float*)d_out;

    float *y, *qkv, *ob, *pb;
    cudaGetSymbolAddress((void**)&y,   g_y);
    cudaGetSymbolAddress((void**)&qkv, g_qkv);
    cudaGetSymbolAddress((void**)&ob,  g_o);
    cudaGetSymbolAddress((void**)&pb,  g_p);

    cudaFuncSetAttribute(attn_kernel,
                         cudaFuncAttributeMaxDynamicSharedMemorySize, ATT_SMEM);

    // 1. LayerNorm
    ln_kernel<<<MM, 256>>>(x, g, b, y);

    // 2. qkv = y @ c_attn_w + c_attn_b   [4096 x 3072]
    hgemm_kernel<false, true><<<dim3(3 * DIMM / 128, MM / 128), 256>>>(
        y, caw, cab, qkv, MM, 3 * DIMM, DIMM);

    // 3. L2-normalize q, k head rows in place
    l2n_kernel<<<(MM * HH * 2 * 32) / 256, 256>>>(qkv);

    // 4. causal cosine-sim attention -> merged heads in g_o
    attn_kernel<<<dim3(NN / 64, BB * HH), 256, ATT_SMEM>>>(qkv, ob);

    // 5. p = o @ c_proj_w + c_proj_b
    hgemm_kernel<false, true><<<dim3(DIMM / 128, MM / 128), 256>>>(
        ob, cpw, cpb, pb, MM, DIMM, DIMM);

    // 6. out = p @ to_out_w^T
    hgemm_kernel<true, false><<<dim3(DIMM / 128, MM / 128), 256>>>(
        pb, tow, (const float*)nullptr, out, MM, DIMM, DIMM);
}

// round 4
// speedup vs baseline: 2.8726x; 2.2338x over previous
#include <cuda_runtime.h>
#include <cuda_bf16.h>
#include <cstdint>
#include <math.h>

typedef unsigned int u32;

// Problem constants
#define BB   2
#define NN   2048
#define DIMM 1024
#define HH   16
#define DHH  64
#define MM   (BB*NN)          // 4096 tokens

// Scratch (allocation-free rule: __device__ globals)
__device__ float g_y  [MM * DIMM];                    // LN output
__device__ float g_qkv[MM * 3 * DIMM];                // qkv fp32 (from GEMM)
__device__ __nv_bfloat16 g_qkvh[MM * 3 * DIMM];       // qkv bf16 hi (q/k normed)
__device__ __nv_bfloat16 g_qkvl[MM * 3 * DIMM];       // qkv bf16 lo
__device__ float g_o  [MM * DIMM];                    // attention out
__device__ float g_p  [MM * DIMM];                    // c_proj out

__device__ __forceinline__ float warp_sum(float v) {
#pragma unroll
    for (int o = 16; o; o >>= 1) v += __shfl_xor_sync(0xffffffffu, v, o);
    return v;
}

// ---------------------------------------------------------------------------
// MMA / ldmatrix / split helpers
// ---------------------------------------------------------------------------
__device__ __forceinline__ void ldm4(u32* r, const __nv_bfloat16* p) {
    u32 a = (u32)__cvta_generic_to_shared(p);
    asm volatile("ldmatrix.sync.aligned.m8n8.x4.shared.b16 {%0,%1,%2,%3}, [%4];"
        : "=r"(r[0]), "=r"(r[1]), "=r"(r[2]), "=r"(r[3]) : "r"(a));
}
__device__ __forceinline__ void ldm4t(u32* r, const __nv_bfloat16* p) {
    u32 a = (u32)__cvta_generic_to_shared(p);
    asm volatile("ldmatrix.sync.aligned.m8n8.x4.trans.shared.b16 {%0,%1,%2,%3}, [%4];"
        : "=r"(r[0]), "=r"(r[1]), "=r"(r[2]), "=r"(r[3]) : "r"(a));
}
__device__ __forceinline__ void mma16816(float* c, const u32* a, const u32* b) {
    asm volatile("mma.sync.aligned.m16n8k16.row.col.f32.bf16.bf16.f32 "
        "{%0,%1,%2,%3}, {%4,%5,%6,%7}, {%8,%9}, {%0,%1,%2,%3};"
        : "+f"(c[0]), "+f"(c[1]), "+f"(c[2]), "+f"(c[3])
        : "r"(a[0]), "r"(a[1]), "r"(a[2]), "r"(a[3]), "r"(b[0]), "r"(b[1]));
}
__device__ __forceinline__ u32 p2(float a, float b) {
    __nv_bfloat162 t = __floats2bfloat162_rn(a, b);
    return *reinterpret_cast<u32*>(&t);
}
__device__ __forceinline__ void split2(float a, float b, u32& hi, u32& lo) {
    float ha = __bfloat162float(__float2bfloat16_rn(a));
    float hb = __bfloat162float(__float2bfloat16_rn(b));
    hi = p2(a, b);
    lo = p2(a - ha, b - hb);
}
__device__ __forceinline__ void split_store4(float4 v, __nv_bfloat16* ph,
                                             __nv_bfloat16* pl) {
    float hx = __bfloat162float(__float2bfloat16_rn(v.x));
    float hy = __bfloat162float(__float2bfloat16_rn(v.y));
    float hz = __bfloat162float(__float2bfloat16_rn(v.z));
    float hw = __bfloat162float(__float2bfloat16_rn(v.w));
    *reinterpret_cast<uint2*>(ph) = make_uint2(p2(hx, hy), p2(hz, hw));
    *reinterpret_cast<uint2*>(pl) =
        make_uint2(p2(v.x - hx, v.y - hy), p2(v.z - hz, v.w - hw));
}

// ---------------------------------------------------------------------------
// LayerNorm
// ---------------------------------------------------------------------------
__global__ void __launch_bounds__(256) ln_kernel(const float* __restrict__ x,
                                                 const float* __restrict__ g,
                                                 const float* __restrict__ b,
                                                 float* __restrict__ y) {
    int row = blockIdx.x;
    int t = threadIdx.x;
    const float* xr = x + (size_t)row * DIMM;
    float4 v = *(const float4*)(xr + t * 4);
    float s  = v.x + v.y + v.z + v.w;
    float ss = v.x*v.x + v.y*v.y + v.z*v.z + v.w*v.w;
    __shared__ float red[16];
    float s1 = warp_sum(s), s2 = warp_sum(ss);
    int w = t >> 5, lane = t & 31;
    if (lane == 0) { red[w] = s1; red[8 + w] = s2; }
    __syncthreads();
    float tot = 0.f, tot2 = 0.f;
#pragma unroll
    for (int i = 0; i < 8; i++) { tot += red[i]; tot2 += red[8 + i]; }
    float mu  = tot  * (1.f / DIMM);
    float var = tot2 * (1.f / DIMM) - mu * mu;
    float inv = rsqrtf(var + 1e-5f);
    float4 gv = *(const float4*)(g + t * 4);
    float4 bv = *(const float4*)(b + t * 4);
    float4 o;
    o.x = (v.x - mu) * inv * gv.x + bv.x;
    o.y = (v.y - mu) * inv * gv.y + bv.y;
    o.z = (v.z - mu) * inv * gv.z + bv.z;
    o.w = (v.w - mu) * inv * gv.w + bv.w;
    *(float4*)(y + (size_t)row * DIMM + t * 4) = o;
}

// ---------------------------------------------------------------------------
// L2-normalize q/k (per head) + split everything to bf16 hi/lo.
// One warp per 64-elem segment. seg: 0-15 q heads, 16-31 k heads, 32-47 v.
// ---------------------------------------------------------------------------
__global__ void __launch_bounds__(256) l2nsplit_kernel(
        const float* __restrict__ qkv,
        __nv_bfloat16* __restrict__ qh, __nv_bfloat16* __restrict__ ql) {
    int gw   = (blockIdx.x * 256 + threadIdx.x) >> 5;
    int lane = threadIdx.x & 31;
    int token = gw / 48;
    int seg   = gw % 48;
    size_t off = (size_t)token * (3 * DIMM) + (size_t)seg * DHH;
    const float* p = qkv + off;
    float a = p[lane], c = p[lane + 32];
    if (seg < 32) {
        float ss = warp_sum(a * a + c * c);
        float inv = 1.f / fmaxf(sqrtf(ss), 1e-12f);
        a *= inv; c *= inv;
    }
    float ha = __bfloat162float(__float2bfloat16_rn(a));
    float hc = __bfloat162float(__float2bfloat16_rn(c));
    qh[off + lane]      = __float2bfloat16_rn(a);
    qh[off + lane + 32] = __float2bfloat16_rn(c);
    ql[off + lane]      = __float2bfloat16_rn(a - ha);
    ql[off + lane + 32] = __float2bfloat16_rn(c - hc);
}

// ---------------------------------------------------------------------------
// bf16x3 tensor-core GEMM (unchanged from R3)
// ---------------------------------------------------------------------------
#define SAK 24
#define SBN 136
#define SBT 24

template <bool TRANSB, bool HASBIAS>
__global__ void __launch_bounds__(256) hgemm_kernel(const float* __restrict__ A,
                                                    const float* __restrict__ Bm,
                                                    const float* __restrict__ bias,
                                                    float* __restrict__ C,
                                                    int M, int N, int K) {
    __shared__ __align__(16) __nv_bfloat16 As_h[128 * SAK];
    __shared__ __align__(16) __nv_bfloat16 As_l[128 * SAK];
    __shared__ __align__(16) __nv_bfloat16 Bs_h[3072];
    __shared__ __align__(16) __nv_bfloat16 Bs_l[3072];

    int tid = threadIdx.x;
    int bm = blockIdx.y * 128, bn = blockIdx.x * 128;

    int ar = tid >> 2, ac = (tid & 3) * 4;
    const float* Ap0 = A + (size_t)(bm + ar) * K + ac;
    const float* Ap1 = Ap0 + (size_t)64 * K;

    const float* Bp0;
    const float* Bp1;
    int bkr = 0, bnc = 0, tnr = 0, tkc = 0;
    if (!TRANSB) {
        bkr = tid >> 4;
        bnc = (tid & 15) * 8;
        Bp0 = Bm + (size_t)bkr * N + bn + bnc;
        Bp1 = Bp0 + 4;
    } else {
        tnr = tid >> 1;
        tkc = (tid & 1) * 8;
        Bp0 = Bm + (size_t)(bn + tnr) * K + tkc;
        Bp1 = Bp0 + 4;
    }

    float4 ra0 = *(const float4*)Ap0;
    float4 ra1 = *(const float4*)Ap1;
    float4 rb0 = *(const float4*)Bp0;
    float4 rb1 = *(const float4*)Bp1;

    int wid = tid >> 5, lane = tid & 31;
    int wm = (wid & 3) * 32, wn = (wid >> 2) * 64;
    int grp = lane >> 3, lr = lane & 7;

    int aidx[2];
    {
        int arow = wm + ((grp & 1) << 3) + lr;
        int acol = (grp & 2) ? 8 : 0;
        aidx[0] = arow * SAK + acol;
        aidx[1] = (arow + 16) * SAK + acol;
    }
    int bidx[4];
#pragma unroll
    for (int nb = 0; nb < 4; nb++) {
        if (!TRANSB) {
            int krow = ((grp & 1) << 3) + lr;
            int ncol = wn + nb * 16 + ((grp & 2) ? 8 : 0);
            bidx[nb] = krow * SBN + ncol;
        } else {
            int nrow = wn + nb * 16 + ((grp & 2) ? 8 : 0) + lr;
            int kcol = (grp & 1) ? 8 : 0;
            bidx[nb] = nrow * SBT + kcol;
        }
    }

    float acc[2][8][4];
#pragma unroll
    for (int i = 0; i < 2; i++)
#pragma unroll
        for (int j = 0; j < 8; j++)
#pragma unroll
            for (int q = 0; q < 4; q++) acc[i][j][q] = 0.f;

    for (int k0 = 0; k0 < K; k0 += 16) {
        split_store4(ra0, &As_h[ar * SAK + ac], &As_l[ar * SAK + ac]);
        split_store4(ra1, &As_h[(ar + 64) * SAK + ac], &As_l[(ar + 64) * SAK + ac]);
        if (!TRANSB) {
            split_store4(rb0, &Bs_h[bkr * SBN + bnc], &Bs_l[bkr * SBN + bnc]);
            split_store4(rb1, &Bs_h[bkr * SBN + bnc + 4], &Bs_l[bkr * SBN + bnc + 4]);
        } else {
            split_store4(rb0, &Bs_h[tnr * SBT + tkc], &Bs_l[tnr * SBT + tkc]);
            split_store4(rb1, &Bs_h[tnr * SBT + tkc + 4], &Bs_l[tnr * SBT + tkc + 4]);
        }
        __syncthreads();

        if (k0 + 16 < K) {
            Ap0 += 16; Ap1 += 16;
            ra0 = *(const float4*)Ap0;
            ra1 = *(const float4*)Ap1;
            if (!TRANSB) { Bp0 += (size_t)16 * N; Bp1 += (size_t)16 * N; }
            else         { Bp0 += 16;             Bp1 += 16; }
            rb0 = *(const float4*)Bp0;
            rb1 = *(const float4*)Bp1;
        }

        u32 ah[2][4], al[2][4];
        ldm4(ah[0], &As_h[aidx[0]]);
        ldm4(ah[1], &As_h[aidx[1]]);
        ldm4(al[0], &As_l[aidx[0]]);
        ldm4(al[1], &As_l[aidx[1]]);

        u32 bh[8][2], bl[8][2];
#pragma unroll
        for (int nb = 0; nb < 4; nb++) {
            u32 r[4];
            if (!TRANSB) ldm4t(r, &Bs_h[bidx[nb]]);
            else         ldm4 (r, &Bs_h[bidx[nb]]);
            bh[2 * nb][0] = r[0]; bh[2 * nb][1] = r[1];
            bh[2 * nb + 1][0] = r[2]; bh[2 * nb + 1][1] = r[3];
            if (!TRANSB) ldm4t(r, &Bs_l[bidx[nb]]);
            else         ldm4 (r, &Bs_l[bidx[nb]]);
            bl[2 * nb][0] = r[0]; bl[2 * nb][1] = r[1];
            bl[2 * nb + 1][0] = r[2]; bl[2 * nb + 1][1] = r[3];
        }

#pragma unroll
        for (int mi = 0; mi < 2; mi++)
#pragma unroll
            for (int nf = 0; nf < 8; nf++) {
                mma16816(acc[mi][nf], ah[mi], bh[nf]);
                mma16816(acc[mi][nf], ah[mi], bl[nf]);
                mma16816(acc[mi][nf], al[mi], bh[nf]);
            }
        __syncthreads();
    }

    int r = lane >> 2, c2 = (lane & 3) * 2;
#pragma unroll
    for (int nf = 0; nf < 8; nf++) {
        int col = bn + wn + nf * 8 + c2;
        float b0v = 0.f, b1v = 0.f;
        if (HASBIAS) { b0v = bias[col]; b1v = bias[col + 1]; }
#pragma unroll
        for (int mi = 0; mi < 2; mi++) {
            int row0 = bm + wm + mi * 16 + r;
            float2 v0 = make_float2(acc[mi][nf][0] + b0v, acc[mi][nf][1] + b1v);
            float2 v1 = make_float2(acc[mi][nf][2] + b0v, acc[mi][nf][3] + b1v);
            *(float2*)(C + (size_t)row0 * N + col) = v0;
            *(float2*)(C + (size_t)(row0 + 8) * N + col) = v1;
        }
    }
}

// ---------------------------------------------------------------------------
// Tensor-core causal flash-attention (bf16x3, fp32 softmax).
// Block = 64 q-rows x (b,h). 4 warps, each owns 16 q-rows.
// S = Qh.Kh + Ql.Kh + Qh.Kl ; O += Ph.Vh + Pl.Vh + Ph.Vl (fp32 accum).
// P(C-frag) == A-frag layout for PV: register-to-register, no smem round-trip.
// ---------------------------------------------------------------------------
#define KST 72   // smem row stride (bf16 elems)

__global__ void __launch_bounds__(128) attn_mma_kernel(
        const __nv_bfloat16* __restrict__ qkvh,
        const __nv_bfloat16* __restrict__ qkvl,
        float* __restrict__ o) {
    __shared__ __align__(16) __nv_bfloat16 skh[64 * KST];
    __shared__ __align__(16) __nv_bfloat16 skl[64 * KST];
    __shared__ __align__(16) __nv_bfloat16 svh[64 * KST];
    __shared__ __align__(16) __nv_bfloat16 svl[64 * KST];

    int bh_ = blockIdx.y;
    int b = bh_ >> 4, h = bh_ & 15;
    int q0 = blockIdx.x * 64;
    int tid = threadIdx.x, wid = tid >> 5, lane = tid & 31;
    int grp = lane >> 3, lr = lane & 7;
    int wm = wid * 16;

    const size_t rs = 3 * DIMM;
    const __nv_bfloat16* qh_base = qkvh + (size_t)b * NN * rs + h * DHH;
    const __nv_bfloat16* ql_base = qkvl + (size_t)b * NN * rs + h * DHH;

    // ---- stage Q tile through skh/skl, extract per-warp fragments ----
    for (int i = tid; i < 64 * 8; i += 128) {
        int r = i >> 3, c = (i & 7) * 8;
        size_t off = (size_t)(q0 + r) * rs + c;
        *(uint4*)&skh[r * KST + c] = *(const uint4*)(qh_base + off);
        *(uint4*)&skl[r * KST + c] = *(const uint4*)(ql_base + off);
    }
    __syncthreads();
    u32 aq_h[4][4], aq_l[4][4];
    {
        int arow = wm + ((grp & 1) << 3) + lr;
#pragma unroll
        for (int ks = 0; ks < 4; ks++) {
            int acol = ks * 16 + ((grp & 2) ? 8 : 0);
            ldm4(aq_h[ks], &skh[arow * KST + acol]);
            ldm4(aq_l[ks], &skl[arow * KST + acol]);
        }
    }

    float m0 = -1e30f, m1 = -1e30f, l0 = 0.f, l1 = 0.f;
    float acc[8][4];
#pragma unroll
    for (int i = 0; i < 8; i++)
#pragma unroll
        for (int j = 0; j < 4; j++) acc[i][j] = 0.f;

    const __nv_bfloat16* kh_base = qh_base + DIMM;
    const __nv_bfloat16* kl_base = ql_base + DIMM;
    const __nv_bfloat16* vh_base = qh_base + 2 * DIMM;
    const __nv_bfloat16* vl_base = ql_base + 2 * DIMM;

    int c2 = (lane & 3) * 2;
    int qrow0 = q0 + wm + (lane >> 2);
    int qrow1 = qrow0 + 8;

    for (int j0 = 0; j0 <= q0; j0 += 64) {
        __syncthreads();   // previous tile fully consumed
        for (int i = tid; i < 64 * 8; i += 128) {
            int r = i >> 3, c = (i & 7) * 8;
            size_t off = (size_t)(j0 + r) * rs + c;
            *(uint4*)&skh[r * KST + c] = *(const uint4*)(kh_base + off);
            *(uint4*)&skl[r * KST + c] = *(const uint4*)(kl_base + off);
            *(uint4*)&svh[r * KST + c] = *(const uint4*)(vh_base + off);
            *(uint4*)&svl[r * KST + c] = *(const uint4*)(vl_base + off);
        }
        __syncthreads();

        // ---- S = Q.K^T ----
        float s[8][4];
#pragma unroll
        for (int i = 0; i < 8; i++)
#pragma unroll
            for (int j = 0; j < 4; j++) s[i][j] = 0.f;

#pragma unroll
        for (int ks = 0; ks < 4; ks++) {
            int kcol = ks * 16 + ((grp & 1) ? 8 : 0);
            u32 kh[4][4], kl[4][4];
#pragma unroll
            for (int nb = 0; nb < 4; nb++) {
                int nrow = nb * 16 + ((grp & 2) ? 8 : 0) + lr;
                ldm4(kh[nb], &skh[nrow * KST + kcol]);
                ldm4(kl[nb], &skl[nrow * KST + kcol]);
            }
#pragma unroll
            for (int nb = 0; nb < 4; nb++) {
                mma16816(s[2 * nb],     aq_h[ks], &kh[nb][0]);
                mma16816(s[2 * nb],     aq_l[ks], &kh[nb][0]);
                mma16816(s[2 * nb],     aq_h[ks], &kl[nb][0]);
                mma16816(s[2 * nb + 1], aq_h[ks], &kh[nb][2]);
                mma16816(s[2 * nb + 1], aq_l[ks], &kh[nb][2]);
                mma16816(s[2 * nb + 1], aq_h[ks], &kl[nb][2]);
            }
        }

        // ---- scale + mask + online softmax ----
        float mx0 = -1e30f, mx1 = -1e30f;
#pragma unroll
        for (int nf = 0; nf < 8; nf++) {
            int key = j0 + nf * 8 + c2;
#pragma unroll
            for (int c = 0; c < 2; c++) {
                float v0 = s[nf][c] * 8.0f;
                float v1 = s[nf][2 + c] * 8.0f;
                if (key + c > qrow0) v0 = -1e30f;
                if (key + c > qrow1) v1 = -1e30f;
                s[nf][c] = v0; s[nf][2 + c] = v1;
                mx0 = fmaxf(mx0, v0); mx1 = fmaxf(mx1, v1);
            }
        }
        mx0 = fmaxf(mx0, __shfl_xor_sync(0xffffffffu, mx0, 1));
        mx0 = fmaxf(mx0, __shfl_xor_sync(0xffffffffu, mx0, 2));
        mx1 = fmaxf(mx1, __shfl_xor_sync(0xffffffffu, mx1, 1));
        mx1 = fmaxf(mx1, __shfl_xor_sync(0xffffffffu, mx1, 2));
        float nm0 = fmaxf(m0, mx0), nm1 = fmaxf(m1, mx1);
        float al0 = __expf(m0 - nm0), al1 = __expf(m1 - nm1);
        m0 = nm0; m1 = nm1;

        float ls0 = 0.f, ls1 = 0.f;
        u32 ph[4][4], pl[4][4];
#pragma unroll
        for (int j = 0; j < 4; j++) {
            float e0 = __expf(s[2 * j][0] - m0);
            float e1 = __expf(s[2 * j][1] - m0);
            float e2 = __expf(s[2 * j][2] - m1);
            float e3 = __expf(s[2 * j][3] - m1);
            float e4 = __expf(s[2 * j + 1][0] - m0);
            float e5 = __expf(s[2 * j + 1][1] - m0);
            float e6 = __expf(s[2 * j + 1][2] - m1);
            float e7 = __expf(s[2 * j + 1][3] - m1);
            ls0 += e0 + e1 + e4 + e5;
            ls1 += e2 + e3 + e6 + e7;
            split2(e0, e1, ph[j][0], pl[j][0]);
            split2(e2, e3, ph[j][1], pl[j][1]);
            split2(e4, e5, ph[j][2], pl[j][2]);
            split2(e6, e7, ph[j][3], pl[j][3]);
        }
        ls0 += __shfl_xor_sync(0xffffffffu, ls0, 1);
        ls0 += __shfl_xor_sync(0xffffffffu, ls0, 2);
        ls1 += __shfl_xor_sync(0xffffffffu, ls1, 1);
        ls1 += __shfl_xor_sync(0xffffffffu, ls1, 2);
        l0 = l0 * al0 + ls0;
        l1 = l1 * al1 + ls1;
#pragma unroll
        for (int nf = 0; nf < 8; nf++) {
            acc[nf][0] *= al0; acc[nf][1] *= al0;
            acc[nf][2] *= al1; acc[nf][3] *= al1;
        }

        // ---- O += P.V ----
#pragma unroll
        for (int ks = 0; ks < 4; ks++) {
            int krow = ks * 16 + ((grp & 1) ? 8 : 0) + lr;
            u32 vh[4][4], vl[4][4];
#pragma unroll
            for (int nb = 0; nb < 4; nb++) {
                int ncol = nb * 16 + ((grp & 2) ? 8 : 0);
                ldm4t(vh[nb], &svh[krow * KST + ncol]);
                ldm4t(vl[nb], &svl[krow * KST + ncol]);
            }
#pragma unroll
            for (int nb = 0; nb < 4; nb++) {
                mma16816(acc[2 * nb],     ph[ks], &vh[nb][0]);
                mma16816(acc[2 * nb],     pl[ks], &vh[nb][0]);
                mma16816(acc[2 * nb],     ph[ks], &vl[nb][0]);
                mma16816(acc[2 * nb + 1], ph[ks], &vh[nb][2]);
                mma16816(acc[2 * nb + 1], pl[ks], &vh[nb][2]);
                mma16816(acc[2 * nb + 1], ph[ks], &vl[nb][2]);
            }
        }
    }

    // ---- epilogue ----
    float inv0 = 1.f / l0, inv1 = 1.f / l1;
    float* op0 = o + ((size_t)(b * NN) + qrow0) * DIMM + h * DHH;
    float* op1 = op0 + (size_t)8 * DIMM;
#pragma unroll
    for (int nf = 0; nf < 8; nf++) {
        *(float2*)(op0 + nf * 8 + c2) =
            make_float2(acc[nf][0] * inv0, acc[nf][1] * inv0);
        *(float2*)(op1 + nf * 8 + c2) =
            make_float2(acc[nf][2] * inv1, acc[nf][3] * inv1);
    }
}

// ---------------------------------------------------------------------------
extern "C" void kernel_launch(void* const* d_in, const int* in_sizes, int n_in,
                              void* d_out, int out_size) {
    const float* x   = (const float*)d_in[0];
    const float* g   = (const float*)d_in[1];
    const float* b   = (const float*)d_in[2];
    const float* caw = (const float*)d_in[3];
    const float* cab = (const float*)d_in[4];
    const float* cpw = (const float*)d_in[5];
    const float* cpb = (const float*)d_in[6];
    const float* tow = (const float*)d_in[7];
    float* out = (float*)d_out;

    float *y, *qkv, *ob, *pb;
    __nv_bfloat16 *qh, *ql;
    cudaGetSymbolAddress((void**)&y,   g_y);
    cudaGetSymbolAddress((void**)&qkv, g_qkv);
    cudaGetSymbolAddress((void**)&qh,  g_qkvh);
    cudaGetSymbolAddress((void**)&ql,  g_qkvl);
    cudaGetSymbolAddress((void**)&ob,  g_o);
    cudaGetSymbolAddress((void**)&pb,  g_p);

    // 1. LayerNorm
    ln_kernel<<<MM, 256>>>(x, g, b, y);

    // 2. qkv = y @ c_attn_w + c_attn_b   [4096 x 3072]
    hgemm_kernel<false, true><<<dim3(3 * DIMM / 128, MM / 128), 256>>>(
        y, caw, cab, qkv, MM, 3 * DIMM, DIMM);

    // 3. L2-normalize q,k per head + split all of qkv to bf16 hi/lo
    l2nsplit_kernel<<<(MM * 48) / 8, 256>>>(qkv, qh, ql);

    // 4. tensor-core causal attention -> merged heads in g_o
    attn_mma_kernel<<<dim3(NN / 64, BB * HH), 128>>>(qh, ql, ob);

    // 5. p = o @ c_proj_w + c_proj_b
    hgemm_kernel<false, true><<<dim3(DIMM / 128, MM / 128), 256>>>(
        ob, cpw, cpb, pb, MM, DIMM, DIMM);

    // 6. out = p @ to_out_w^T
    hgemm_kernel<true, false><<<dim3(DIMM / 128, MM / 128), 256>>>(
        pb, tow, (const float*)nullptr, out, MM, DIMM, DIMM);
}

// round 5
// speedup vs baseline: 3.4529x; 1.2020x over previous
#include <cuda_runtime.h>
#include <cuda_bf16.h>
#include <cstdint>
#include <math.h>

typedef unsigned int u32;
typedef __nv_bfloat16 bf16;

// Problem constants
#define BB   2
#define NN   2048
#define DIMM 1024
#define HH   16
#define DHH  64
#define MM   (BB*NN)          // 4096 tokens

// Scratch (allocation-free rule: __device__ globals)
__device__ bf16  g_yh [MM * DIMM];
__device__ bf16  g_yl [MM * DIMM];
__device__ float g_qkv[MM * 3 * DIMM];
__device__ bf16  g_qkvh[MM * 3 * DIMM];
__device__ bf16  g_qkvl[MM * 3 * DIMM];
__device__ bf16  g_oh [MM * DIMM];
__device__ bf16  g_ol [MM * DIMM];
__device__ bf16  g_ph [MM * DIMM];
__device__ bf16  g_pl [MM * DIMM];
__device__ bf16  g_cawh[DIMM * 3 * DIMM];
__device__ bf16  g_cawl[DIMM * 3 * DIMM];
__device__ bf16  g_cpwh[DIMM * DIMM];
__device__ bf16  g_cpwl[DIMM * DIMM];
__device__ bf16  g_towh[DIMM * DIMM];
__device__ bf16  g_towl[DIMM * DIMM];

__device__ __forceinline__ float warp_sum(float v) {
#pragma unroll
    for (int o = 16; o; o >>= 1) v += __shfl_xor_sync(0xffffffffu, v, o);
    return v;
}

// ---------------------------------------------------------------------------
// MMA / ldmatrix / cp.async / split helpers
// ---------------------------------------------------------------------------
__device__ __forceinline__ void ldm4(u32* r, const bf16* p) {
    u32 a = (u32)__cvta_generic_to_shared(p);
    asm volatile("ldmatrix.sync.aligned.m8n8.x4.shared.b16 {%0,%1,%2,%3}, [%4];"
        : "=r"(r[0]), "=r"(r[1]), "=r"(r[2]), "=r"(r[3]) : "r"(a));
}
__device__ __forceinline__ void ldm4t(u32* r, const bf16* p) {
    u32 a = (u32)__cvta_generic_to_shared(p);
    asm volatile("ldmatrix.sync.aligned.m8n8.x4.trans.shared.b16 {%0,%1,%2,%3}, [%4];"
        : "=r"(r[0]), "=r"(r[1]), "=r"(r[2]), "=r"(r[3]) : "r"(a));
}
__device__ __forceinline__ void mma16816(float* c, const u32* a, const u32* b) {
    asm volatile("mma.sync.aligned.m16n8k16.row.col.f32.bf16.bf16.f32 "
        "{%0,%1,%2,%3}, {%4,%5,%6,%7}, {%8,%9}, {%0,%1,%2,%3};"
        : "+f"(c[0]), "+f"(c[1]), "+f"(c[2]), "+f"(c[3])
        : "r"(a[0]), "r"(a[1]), "r"(a[2]), "r"(a[3]), "r"(b[0]), "r"(b[1]));
}
__device__ __forceinline__ void cpa16(bf16* dst, const bf16* src) {
    u32 d = (u32)__cvta_generic_to_shared(dst);
    asm volatile("cp.async.cg.shared.global [%0], [%1], 16;" :: "r"(d), "l"(src));
}
__device__ __forceinline__ void cpa_commit() {
    asm volatile("cp.async.commit_group;");
}
__device__ __forceinline__ void cpa_wait0() {
    asm volatile("cp.async.wait_group 0;");
}
__device__ __forceinline__ u32 p2(float a, float b) {
    __nv_bfloat162 t = __floats2bfloat162_rn(a, b);
    return *reinterpret_cast<u32*>(&t);
}
__device__ __forceinline__ void split2(float a, float b, u32& hi, u32& lo) {
    float ha = __bfloat162float(__float2bfloat16_rn(a));
    float hb = __bfloat162float(__float2bfloat16_rn(b));
    hi = p2(a, b);
    lo = p2(a - ha, b - hb);
}
__device__ __forceinline__ void split_store4(float4 v, bf16* ph, bf16* pl) {
    float hx = __bfloat162float(__float2bfloat16_rn(v.x));
    float hy = __bfloat162float(__float2bfloat16_rn(v.y));
    float hz = __bfloat162float(__float2bfloat16_rn(v.z));
    float hw = __bfloat162float(__float2bfloat16_rn(v.w));
    *reinterpret_cast<uint2*>(ph) = make_uint2(p2(hx, hy), p2(hz, hw));
    *reinterpret_cast<uint2*>(pl) =
        make_uint2(p2(v.x - hx, v.y - hy), p2(v.z - hz, v.w - hw));
}

// ---------------------------------------------------------------------------
// Generic fp32 -> bf16 hi/lo split (weights), 4 elems/thread
// ---------------------------------------------------------------------------
__global__ void __launch_bounds__(256) split_kernel(const float* __restrict__ in,
                                                    bf16* __restrict__ h,
                                                    bf16* __restrict__ l) {
    int i = (blockIdx.x * 256 + threadIdx.x) * 4;
    float4 v = *(const float4*)(in + i);
    split_store4(v, h + i, l + i);
}

// ---------------------------------------------------------------------------
// LayerNorm -> bf16 hi/lo directly
// ---------------------------------------------------------------------------
__global__ void __launch_bounds__(256) ln_kernel(const float* __restrict__ x,
                                                 const float* __restrict__ g,
                                                 const float* __restrict__ b,
                                                 bf16* __restrict__ yh,
                                                 bf16* __restrict__ yl) {
    int row = blockIdx.x;
    int t = threadIdx.x;
    const float* xr = x + (size_t)row * DIMM;
    float4 v = *(const float4*)(xr + t * 4);
    float s  = v.x + v.y + v.z + v.w;
    float ss = v.x*v.x + v.y*v.y + v.z*v.z + v.w*v.w;
    __shared__ float red[16];
    float s1 = warp_sum(s), s2 = warp_sum(ss);
    int w = t >> 5, lane = t & 31;
    if (lane == 0) { red[w] = s1; red[8 + w] = s2; }
    __syncthreads();
    float tot = 0.f, tot2 = 0.f;
#pragma unroll
    for (int i = 0; i < 8; i++) { tot += red[i]; tot2 += red[8 + i]; }
    float mu  = tot  * (1.f / DIMM);
    float var = tot2 * (1.f / DIMM) - mu * mu;
    float inv = rsqrtf(var + 1e-5f);
    float4 gv = *(const float4*)(g + t * 4);
    float4 bv = *(const float4*)(b + t * 4);
    float4 o;
    o.x = (v.x - mu) * inv * gv.x + bv.x;
    o.y = (v.y - mu) * inv * gv.y + bv.y;
    o.z = (v.z - mu) * inv * gv.z + bv.z;
    o.w = (v.w - mu) * inv * gv.w + bv.w;
    size_t off = (size_t)row * DIMM + t * 4;
    split_store4(o, yh + off, yl + off);
}

// ---------------------------------------------------------------------------
// L2-normalize q/k per head + split qkv to bf16 hi/lo
// ---------------------------------------------------------------------------
__global__ void __launch_bounds__(256) l2nsplit_kernel(
        const float* __restrict__ qkv,
        bf16* __restrict__ qh, bf16* __restrict__ ql) {
    int gw   = (blockIdx.x * 256 + threadIdx.x) >> 5;
    int lane = threadIdx.x & 31;
    int token = gw / 48;
    int seg   = gw % 48;
    size_t off = (size_t)token * (3 * DIMM) + (size_t)seg * DHH;
    const float* p = qkv + off;
    float a = p[lane], c = p[lane + 32];
    if (seg < 32) {
        float ss = warp_sum(a * a + c * c);
        float inv = 1.f / fmaxf(sqrtf(ss), 1e-12f);
        a *= inv; c *= inv;
    }
    float ha = __bfloat162float(__float2bfloat16_rn(a));
    float hc = __bfloat162float(__float2bfloat16_rn(c));
    qh[off + lane]      = __float2bfloat16_rn(a);
    qh[off + lane + 32] = __float2bfloat16_rn(c);
    ql[off + lane]      = __float2bfloat16_rn(a - ha);
    ql[off + lane + 32] = __float2bfloat16_rn(c - hc);
}

// ---------------------------------------------------------------------------
// bf16x3 tensor-core GEMM, pre-split inputs, cp.async 2-stage pipeline.
// C[M,N] = (Ah+Al)(Bh+Bl) ~= AhBh + AlBh + AhBl  (+bias), fp32 accum.
// Block 128x128, BK=32, 256 threads = 8 warps (4m x 2n), warp tile 32x64.
// TRANSB=1: B is [N,K].  OUTSPLIT=1: write bf16 hi/lo instead of fp32.
// ---------------------------------------------------------------------------
#define SA2   40      // A / trans-B smem row stride (bf16 elems)
#define SB2   136     // non-trans B smem row stride
#define STAGE 20480   // bf16 elems per stage (Ah 5120, Al 5120, Bh 5120, Bl 5120)
#define GEMM_SMEM (2 * STAGE * 2)

template <bool TRANSB, bool HASBIAS, bool OUTSPLIT>
__global__ void __launch_bounds__(256) hgemm2_kernel(
        const bf16* __restrict__ Ahg, const bf16* __restrict__ Alg,
        const bf16* __restrict__ Bhg, const bf16* __restrict__ Blg,
        const float* __restrict__ bias,
        float* __restrict__ C, bf16* __restrict__ Ch, bf16* __restrict__ Cl,
        int M, int N, int K) {
    extern __shared__ __align__(16) bf16 smem[];

    int tid = threadIdx.x;
    int bm = blockIdx.y * 128, bn = blockIdx.x * 128;
    int wid = tid >> 5, lane = tid & 31;
    int wm = (wid & 3) * 32, wn = (wid >> 2) * 64;
    int grp = lane >> 3, lr = lane & 7;

    auto load_stage = [&](int s, int k0) {
        bf16* sAh = smem + s * STAGE;
        bf16* sAl = sAh + 5120;
        bf16* sBh = sAh + 10240;
        bf16* sBl = sAh + 15360;
#pragma unroll
        for (int i = 0; i < 2; i++) {
            int c = tid + i * 256;
            int row = c >> 2, kg = (c & 3) * 8;
            size_t src = (size_t)(bm + row) * K + k0 + kg;
            cpa16(&sAh[row * SA2 + kg], Ahg + src);
            cpa16(&sAl[row * SA2 + kg], Alg + src);
        }
        if (!TRANSB) {
#pragma unroll
            for (int i = 0; i < 2; i++) {
                int c = tid + i * 256;
                int row = c >> 4, col = (c & 15) * 8;
                size_t src = (size_t)(k0 + row) * N + bn + col;
                cpa16(&sBh[row * SB2 + col], Bhg + src);
                cpa16(&sBl[row * SB2 + col], Blg + src);
            }
        } else {
#pragma unroll
            for (int i = 0; i < 2; i++) {
                int c = tid + i * 256;
                int row = c >> 2, kg = (c & 3) * 8;
                size_t src = (size_t)(bn + row) * K + k0 + kg;
                cpa16(&sBh[row * SA2 + kg], Bhg + src);
                cpa16(&sBl[row * SA2 + kg], Blg + src);
            }
        }
    };

    float acc[2][8][4];
#pragma unroll
    for (int i = 0; i < 2; i++)
#pragma unroll
        for (int j = 0; j < 8; j++)
#pragma unroll
            for (int q = 0; q < 4; q++) acc[i][j][q] = 0.f;

    int arow0 = wm + ((grp & 1) << 3) + lr;

    load_stage(0, 0);
    cpa_commit();

    const int NK = K / 32;
    int stage = 0;
    for (int it = 0; it < NK; it++) {
        cpa_wait0();
        __syncthreads();
        if (it + 1 < NK) { load_stage(stage ^ 1, (it + 1) * 32); cpa_commit(); }

        bf16* sAh = smem + stage * STAGE;
        bf16* sAl = sAh + 5120;
        bf16* sBh = sAh + 10240;
        bf16* sBl = sAh + 15360;

#pragma unroll
        for (int ks = 0; ks < 2; ks++) {
            int acol = ks * 16 + ((grp & 2) ? 8 : 0);
            u32 ah[2][4], al[2][4];
            ldm4(ah[0], &sAh[arow0 * SA2 + acol]);
            ldm4(ah[1], &sAh[(arow0 + 16) * SA2 + acol]);
            ldm4(al[0], &sAl[arow0 * SA2 + acol]);
            ldm4(al[1], &sAl[(arow0 + 16) * SA2 + acol]);

            u32 bh[8][2], bl[8][2];
#pragma unroll
            for (int nb = 0; nb < 4; nb++) {
                u32 r[4];
                if (!TRANSB) {
                    int krow = ks * 16 + ((grp & 1) << 3) + lr;
                    int ncol = wn + nb * 16 + ((grp & 2) ? 8 : 0);
                    ldm4t(r, &sBh[krow * SB2 + ncol]);
                    bh[2*nb][0]=r[0]; bh[2*nb][1]=r[1];
                    bh[2*nb+1][0]=r[2]; bh[2*nb+1][1]=r[3];
                    ldm4t(r, &sBl[krow * SB2 + ncol]);
                    bl[2*nb][0]=r[0]; bl[2*nb][1]=r[1];
                    bl[2*nb+1][0]=r[2]; bl[2*nb+1][1]=r[3];
                } else {
                    int nrow = wn + nb * 16 + ((grp & 2) ? 8 : 0) + lr;
                    int kcol = ks * 16 + ((grp & 1) ? 8 : 0);
                    ldm4(r, &sBh[nrow * SA2 + kcol]);
                    bh[2*nb][0]=r[0]; bh[2*nb][1]=r[1];
                    bh[2*nb+1][0]=r[2]; bh[2*nb+1][1]=r[3];
                    ldm4(r, &sBl[nrow * SA2 + kcol]);
                    bl[2*nb][0]=r[0]; bl[2*nb][1]=r[1];
                    bl[2*nb+1][0]=r[2]; bl[2*nb+1][1]=r[3];
                }
            }
#pragma unroll
            for (int mi = 0; mi < 2; mi++)
#pragma unroll
                for (int nf = 0; nf < 8; nf++) {
                    mma16816(acc[mi][nf], ah[mi], bh[nf]);
                    mma16816(acc[mi][nf], al[mi], bh[nf]);
                    mma16816(acc[mi][nf], ah[mi], bl[nf]);
                }
        }
        __syncthreads();
        stage ^= 1;
    }

    // epilogue
    int r = lane >> 2, c2 = (lane & 3) * 2;
#pragma unroll
    for (int nf = 0; nf < 8; nf++) {
        int col = bn + wn + nf * 8 + c2;
        float b0v = 0.f, b1v = 0.f;
        if (HASBIAS) { b0v = bias[col]; b1v = bias[col + 1]; }
#pragma unroll
        for (int mi = 0; mi < 2; mi++) {
            int row0 = bm + wm + mi * 16 + r;
            float v00 = acc[mi][nf][0] + b0v, v01 = acc[mi][nf][1] + b1v;
            float v10 = acc[mi][nf][2] + b0v, v11 = acc[mi][nf][3] + b1v;
            size_t o0 = (size_t)row0 * N + col;
            size_t o1 = (size_t)(row0 + 8) * N + col;
            if (OUTSPLIT) {
                u32 hi, lo;
                split2(v00, v01, hi, lo);
                *(u32*)(Ch + o0) = hi; *(u32*)(Cl + o0) = lo;
                split2(v10, v11, hi, lo);
                *(u32*)(Ch + o1) = hi; *(u32*)(Cl + o1) = lo;
            } else {
                *(float2*)(C + o0) = make_float2(v00, v01);
                *(float2*)(C + o1) = make_float2(v10, v11);
            }
        }
    }
}

// ---------------------------------------------------------------------------
// Tensor-core causal flash-attention (bf16x3, fp32 softmax).
// Epilogue writes bf16 hi/lo (input to c_proj GEMM).
// ---------------------------------------------------------------------------
#define KST 72

__global__ void __launch_bounds__(128) attn_mma_kernel(
        const bf16* __restrict__ qkvh,
        const bf16* __restrict__ qkvl,
        bf16* __restrict__ oh, bf16* __restrict__ ol) {
    __shared__ __align__(16) bf16 skh[64 * KST];
    __shared__ __align__(16) bf16 skl[64 * KST];
    __shared__ __align__(16) bf16 svh[64 * KST];
    __shared__ __align__(16) bf16 svl[64 * KST];

    int bh_ = blockIdx.y;
    int b = bh_ >> 4, h = bh_ & 15;
    int q0 = blockIdx.x * 64;
    int tid = threadIdx.x, wid = tid >> 5, lane = tid & 31;
    int grp = lane >> 3, lr = lane & 7;
    int wm = wid * 16;

    const size_t rs = 3 * DIMM;
    const bf16* qh_base = qkvh + (size_t)b * NN * rs + h * DHH;
    const bf16* ql_base = qkvl + (size_t)b * NN * rs + h * DHH;

    for (int i = tid; i < 64 * 8; i += 128) {
        int r = i >> 3, c = (i & 7) * 8;
        size_t off = (size_t)(q0 + r) * rs + c;
        *(uint4*)&skh[r * KST + c] = *(const uint4*)(qh_base + off);
        *(uint4*)&skl[r * KST + c] = *(const uint4*)(ql_base + off);
    }
    __syncthreads();
    u32 aq_h[4][4], aq_l[4][4];
    {
        int arow = wm + ((grp & 1) << 3) + lr;
#pragma unroll
        for (int ks = 0; ks < 4; ks++) {
            int acol = ks * 16 + ((grp & 2) ? 8 : 0);
            ldm4(aq_h[ks], &skh[arow * KST + acol]);
            ldm4(aq_l[ks], &skl[arow * KST + acol]);
        }
    }

    float m0 = -1e30f, m1 = -1e30f, l0 = 0.f, l1 = 0.f;
    float acc[8][4];
#pragma unroll
    for (int i = 0; i < 8; i++)
#pragma unroll
        for (int j = 0; j < 4; j++) acc[i][j] = 0.f;

    const bf16* kh_base = qh_base + DIMM;
    const bf16* kl_base = ql_base + DIMM;
    const bf16* vh_base = qh_base + 2 * DIMM;
    const bf16* vl_base = ql_base + 2 * DIMM;

    int c2 = (lane & 3) * 2;
    int qrow0 = q0 + wm + (lane >> 2);
    int qrow1 = qrow0 + 8;

    for (int j0 = 0; j0 <= q0; j0 += 64) {
        __syncthreads();
        for (int i = tid; i < 64 * 8; i += 128) {
            int r = i >> 3, c = (i & 7) * 8;
            size_t off = (size_t)(j0 + r) * rs + c;
            *(uint4*)&skh[r * KST + c] = *(const uint4*)(kh_base + off);
            *(uint4*)&skl[r * KST + c] = *(const uint4*)(kl_base + off);
            *(uint4*)&svh[r * KST + c] = *(const uint4*)(vh_base + off);
            *(uint4*)&svl[r * KST + c] = *(const uint4*)(vl_base + off);
        }
        __syncthreads();

        float s[8][4];
#pragma unroll
        for (int i = 0; i < 8; i++)
#pragma unroll
            for (int j = 0; j < 4; j++) s[i][j] = 0.f;

#pragma unroll
        for (int ks = 0; ks < 4; ks++) {
            int kcol = ks * 16 + ((grp & 1) ? 8 : 0);
            u32 kh[4][4], kl[4][4];
#pragma unroll
            for (int nb = 0; nb < 4; nb++) {
                int nrow = nb * 16 + ((grp & 2) ? 8 : 0) + lr;
                ldm4(kh[nb], &skh[nrow * KST + kcol]);
                ldm4(kl[nb], &skl[nrow * KST + kcol]);
            }
#pragma unroll
            for (int nb = 0; nb < 4; nb++) {
                mma16816(s[2 * nb],     aq_h[ks], &kh[nb][0]);
                mma16816(s[2 * nb],     aq_l[ks], &kh[nb][0]);
                mma16816(s[2 * nb],     aq_h[ks], &kl[nb][0]);
                mma16816(s[2 * nb + 1], aq_h[ks], &kh[nb][2]);
                mma16816(s[2 * nb + 1], aq_l[ks], &kh[nb][2]);
                mma16816(s[2 * nb + 1], aq_h[ks], &kl[nb][2]);
            }
        }

        float mx0 = -1e30f, mx1 = -1e30f;
#pragma unroll
        for (int nf = 0; nf < 8; nf++) {
            int key = j0 + nf * 8 + c2;
#pragma unroll
            for (int c = 0; c < 2; c++) {
                float v0 = s[nf][c] * 8.0f;
                float v1 = s[nf][2 + c] * 8.0f;
                if (key + c > qrow0) v0 = -1e30f;
                if (key + c > qrow1) v1 = -1e30f;
                s[nf][c] = v0; s[nf][2 + c] = v1;
                mx0 = fmaxf(mx0, v0); mx1 = fmaxf(mx1, v1);
            }
        }
        mx0 = fmaxf(mx0, __shfl_xor_sync(0xffffffffu, mx0, 1));
        mx0 = fmaxf(mx0, __shfl_xor_sync(0xffffffffu, mx0, 2));
        mx1 = fmaxf(mx1, __shfl_xor_sync(0xffffffffu, mx1, 1));
        mx1 = fmaxf(mx1, __shfl_xor_sync(0xffffffffu, mx1, 2));
        float nm0 = fmaxf(m0, mx0), nm1 = fmaxf(m1, mx1);
        float al0 = __expf(m0 - nm0), al1 = __expf(m1 - nm1);
        m0 = nm0; m1 = nm1;

        float ls0 = 0.f, ls1 = 0.f;
        u32 ph[4][4], pl[4][4];
#pragma unroll
        for (int j = 0; j < 4; j++) {
            float e0 = __expf(s[2 * j][0] - m0);
            float e1 = __expf(s[2 * j][1] - m0);
            float e2 = __expf(s[2 * j][2] - m1);
            float e3 = __expf(s[2 * j][3] - m1);
            float e4 = __expf(s[2 * j + 1][0] - m0);
            float e5 = __expf(s[2 * j + 1][1] - m0);
            float e6 = __expf(s[2 * j + 1][2] - m1);
            float e7 = __expf(s[2 * j + 1][3] - m1);
            ls0 += e0 + e1 + e4 + e5;
            ls1 += e2 + e3 + e6 + e7;
            split2(e0, e1, ph[j][0], pl[j][0]);
            split2(e2, e3, ph[j][1], pl[j][1]);
            split2(e4, e5, ph[j][2], pl[j][2]);
            split2(e6, e7, ph[j][3], pl[j][3]);
        }
        ls0 += __shfl_xor_sync(0xffffffffu, ls0, 1);
        ls0 += __shfl_xor_sync(0xffffffffu, ls0, 2);
        ls1 += __shfl_xor_sync(0xffffffffu, ls1, 1);
        ls1 += __shfl_xor_sync(0xffffffffu, ls1, 2);
        l0 = l0 * al0 + ls0;
        l1 = l1 * al1 + ls1;
#pragma unroll
        for (int nf = 0; nf < 8; nf++) {
            acc[nf][0] *= al0; acc[nf][1] *= al0;
            acc[nf][2] *= al1; acc[nf][3] *= al1;
        }

#pragma unroll
        for (int ks = 0; ks < 4; ks++) {
            int krow = ks * 16 + ((grp & 1) ? 8 : 0) + lr;
            u32 vh[4][4], vl[4][4];
#pragma unroll
            for (int nb = 0; nb < 4; nb++) {
                int ncol = nb * 16 + ((grp & 2) ? 8 : 0);
                ldm4t(vh[nb], &svh[krow * KST + ncol]);
                ldm4t(vl[nb], &svl[krow * KST + ncol]);
            }
#pragma unroll
            for (int nb = 0; nb < 4; nb++) {
                mma16816(acc[2 * nb],     ph[ks], &vh[nb][0]);
                mma16816(acc[2 * nb],     pl[ks], &vh[nb][0]);
                mma16816(acc[2 * nb],     ph[ks], &vl[nb][0]);
                mma16816(acc[2 * nb + 1], ph[ks], &vh[nb][2]);
                mma16816(acc[2 * nb + 1], pl[ks], &vh[nb][2]);
                mma16816(acc[2 * nb + 1], ph[ks], &vl[nb][2]);
            }
        }
    }

    // epilogue -> bf16 hi/lo
    float inv0 = 1.f / l0, inv1 = 1.f / l1;
    size_t o0 = ((size_t)(b * NN) + qrow0) * DIMM + h * DHH;
    size_t o1 = o0 + (size_t)8 * DIMM;
#pragma unroll
    for (int nf = 0; nf < 8; nf++) {
        u32 hi, lo;
        split2(acc[nf][0] * inv0, acc[nf][1] * inv0, hi, lo);
        *(u32*)(oh + o0 + nf * 8 + c2) = hi;
        *(u32*)(ol + o0 + nf * 8 + c2) = lo;
        split2(acc[nf][2] * inv1, acc[nf][3] * inv1, hi, lo);
        *(u32*)(oh + o1 + nf * 8 + c2) = hi;
        *(u32*)(ol + o1 + nf * 8 + c2) = lo;
    }
}

// ---------------------------------------------------------------------------
extern "C" void kernel_launch(void* const* d_in, const int* in_sizes, int n_in,
                              void* d_out, int out_size) {
    const float* x   = (const float*)d_in[0];
    const float* g   = (const float*)d_in[1];
    const float* b   = (const float*)d_in[2];
    const float* caw = (const float*)d_in[3];
    const float* cab = (const float*)d_in[4];
    const float* cpw = (const float*)d_in[5];
    const float* cpb = (const float*)d_in[6];
    const float* tow = (const float*)d_in[7];
    float* out = (float*)d_out;

    float* qkv;
    bf16 *yh, *yl, *qh, *ql, *oh, *ol, *ph, *pl;
    bf16 *cawh, *cawl, *cpwh, *cpwl, *towh, *towl;
    cudaGetSymbolAddress((void**)&qkv, g_qkv);
    cudaGetSymbolAddress((void**)&yh, g_yh);
    cudaGetSymbolAddress((void**)&yl, g_yl);
    cudaGetSymbolAddress((void**)&qh, g_qkvh);
    cudaGetSymbolAddress((void**)&ql, g_qkvl);
    cudaGetSymbolAddress((void**)&oh, g_oh);
    cudaGetSymbolAddress((void**)&ol, g_ol);
    cudaGetSymbolAddress((void**)&ph, g_ph);
    cudaGetSymbolAddress((void**)&pl, g_pl);
    cudaGetSymbolAddress((void**)&cawh, g_cawh);
    cudaGetSymbolAddress((void**)&cawl, g_cawl);
    cudaGetSymbolAddress((void**)&cpwh, g_cpwh);
    cudaGetSymbolAddress((void**)&cpwl, g_cpwl);
    cudaGetSymbolAddress((void**)&towh, g_towh);
    cudaGetSymbolAddress((void**)&towl, g_towl);

    cudaFuncSetAttribute(hgemm2_kernel<false, true, false>,
        cudaFuncAttributeMaxDynamicSharedMemorySize, GEMM_SMEM);
    cudaFuncSetAttribute(hgemm2_kernel<false, true, true>,
        cudaFuncAttributeMaxDynamicSharedMemorySize, GEMM_SMEM);
    cudaFuncSetAttribute(hgemm2_kernel<true, false, false>,
        cudaFuncAttributeMaxDynamicSharedMemorySize, GEMM_SMEM);

    // 0. split weights to bf16 hi/lo
    split_kernel<<<DIMM * 3 * DIMM / 1024, 256>>>(caw, cawh, cawl);
    split_kernel<<<DIMM * DIMM / 1024, 256>>>(cpw, cpwh, cpwl);
    split_kernel<<<DIMM * DIMM / 1024, 256>>>(tow, towh, towl);

    // 1. LayerNorm -> bf16 hi/lo
    ln_kernel<<<MM, 256>>>(x, g, b, yh, yl);

    // 2. qkv = y @ c_attn_w + c_attn_b (fp32 out, needed by l2 norm)
    hgemm2_kernel<false, true, false>
        <<<dim3(3 * DIMM / 128, MM / 128), 256, GEMM_SMEM>>>(
        yh, yl, cawh, cawl, cab, qkv, nullptr, nullptr, MM, 3 * DIMM, DIMM);

    // 3. L2-normalize q,k per head + split to bf16 hi/lo
    l2nsplit_kernel<<<(MM * 48) / 8, 256>>>(qkv, qh, ql);

    // 4. tensor-core causal attention -> bf16 hi/lo merged heads
    attn_mma_kernel<<<dim3(NN / 64, BB * HH), 128>>>(qh, ql, oh, ol);

    // 5. p = o @ c_proj_w + c_proj_b -> bf16 hi/lo
    hgemm2_kernel<false, true, true>
        <<<dim3(DIMM / 128, MM / 128), 256, GEMM_SMEM>>>(
        oh, ol, cpwh, cpwl, cpb, nullptr, ph, pl, MM, DIMM, DIMM);

    // 6. out = p @ to_out_w^T (fp32 out)
    hgemm2_kernel<true, false, false>
        <<<dim3(DIMM / 128, MM / 128), 256, GEMM_SMEM>>>(
        ph, pl, towh, towl, nullptr, out, nullptr, nullptr, MM, DIMM, DIMM);
}